// round 10
// baseline (speedup 1.0000x reference)
#include <cuda_runtime.h>
#include <cuda_bf16.h>
#include <cstdint>

#define NTOT 1000000
#define N0C  495616
#define N1C  45056
#define N2C  4096
#define E0C  450560
#define E1C  40960
#define DC   128
#define PC   4096

#define NB0  (N1C / 256)        // 176
#define NB1  (N2C / 256)        // 16
#define NBS  (NB0 + NB1)        // 192

// ---------------- device scratch (static, allocation-free) ----------------
__device__ float g_mean0[N1C * DC];
__device__ float g_h1[N1C * DC];
__device__ float g_mean1[N2C * DC];
__device__ float g_h2[N2C * DC];
__device__ int   g_hist0[N1C];
__device__ int   g_off0[N1C + 1];
__device__ int   g_cur0[N1C];
__device__ int   g_hist1[N2C];
__device__ int   g_off1[N2C + 1];
__device__ int   g_cur1[N2C];
__device__ int   g_sorted0[E0C];
__device__ int   g_sorted1[E1C];
__device__ int   g_part[NBS];
__device__ int   g_tot0, g_tot1;

// ---------------- fused histogram over both edge lists ----------------
__global__ void histF_k(const int* __restrict__ ed0, const int* __restrict__ ed1) {
    int e = blockIdx.x * 256 + threadIdx.x;
    if (e < E0C) atomicAdd(&g_hist0[ed0[e]], 1);
    else         atomicAdd(&g_hist1[ed1[e - E0C]], 1);
}

// ---------------- 3-phase scan (both graphs fused) ----------------
__global__ void scanA_k() {
    __shared__ int red[256];
    int b = blockIdx.x, t = threadIdx.x;
    int v = (b < NB0) ? g_hist0[b * 256 + t] : g_hist1[(b - NB0) * 256 + t];
    red[t] = v; __syncthreads();
#pragma unroll
    for (int d = 128; d > 0; d >>= 1) {
        if (t < d) red[t] += red[t + d];
        __syncthreads();
    }
    if (t == 0) g_part[b] = red[0];
}

__global__ void scanB_k() {
    __shared__ int s[NBS];
    int t = threadIdx.x;
    int v = g_part[t];
    s[t] = v; __syncthreads();
#pragma unroll
    for (int d = 1; d < NBS; d <<= 1) {
        int x = (t >= d) ? s[t - d] : 0;
        __syncthreads();
        s[t] += x;
        __syncthreads();
    }
    int tot0 = s[NB0 - 1];
    int excl = s[t] - v;
    if (t >= NB0) excl -= tot0;
    g_part[t] = excl;
    if (t == 0) { g_tot0 = tot0; g_tot1 = s[NBS - 1] - tot0; }
}

__global__ void scanC_k() {
    __shared__ int s[256];
    int b = blockIdx.x, t = threadIdx.x;
    bool is0 = (b < NB0);
    int i = is0 ? b * 256 + t : (b - NB0) * 256 + t;
    int v = is0 ? g_hist0[i] : g_hist1[i];
    s[t] = v; __syncthreads();
#pragma unroll
    for (int d = 1; d < 256; d <<= 1) {
        int x = (t >= d) ? s[t - d] : 0;
        __syncthreads();
        s[t] += x;
        __syncthreads();
    }
    int off = s[t] - v + g_part[b];
    if (is0) { g_off0[i] = off; g_cur0[i] = off; }
    else     { g_off1[i] = off; g_cur1[i] = off; }
    if (t == 255) {
        if (b == NB0 - 1) g_off0[N1C] = g_tot0;
        if (b == NBS - 1) g_off1[N2C] = g_tot1;
    }
}

// ---------------- fused scatter ----------------
__global__ void scatF_k(const int* __restrict__ es0, const int* __restrict__ ed0,
                        const int* __restrict__ es1, const int* __restrict__ ed1,
                        const int* __restrict__ inode) {
    int e = blockIdx.x * 256 + threadIdx.x;
    if (e < E0C) {
        int d = ed0[e];
        int p = atomicAdd(&g_cur0[d], 1);
        g_sorted0[p] = inode[es0[e]];
    } else {
        int k = e - E0C;
        int d = ed1[k];
        int p = atomicAdd(&g_cur1[d], 1);
        g_sorted1[p] = es1[k];
    }
}

// ---------------- neighbor mean aggregation: one warp per dst ----------------
__device__ __forceinline__ void agg_body(const float* __restrict__ feat,
                                         const int* __restrict__ offs,
                                         const int* __restrict__ sorted,
                                         int n_dst, float* __restrict__ mean_out) {
    int w = (int)((blockIdx.x * (long)blockDim.x + threadIdx.x) >> 5);
    int lane = threadIdx.x & 31;
    if (w >= n_dst) return;
    int beg = offs[w], end = offs[w + 1];
    const float4* f4 = (const float4*)feat;
    float4 acc = make_float4(0.f, 0.f, 0.f, 0.f);
    for (int j = beg; j < end; j++) {
        long r = sorted[j];
        float4 v = f4[r * 32 + lane];
        acc.x += v.x; acc.y += v.y; acc.z += v.z; acc.w += v.w;
    }
    float deg = (float)(end - beg);
    float sc = 1.0f / fmaxf(deg, 1.0f);
    ((float4*)mean_out)[(long)w * 32 + lane] =
        make_float4(acc.x * sc, acc.y * sc, acc.z * sc, acc.w * sc);
}
__global__ void agg0_k(const float* __restrict__ nf) { agg_body(nf, g_off0, g_sorted0, N1C, g_mean0); }
__global__ void agg1_k() { agg_body(g_h1, g_off1, g_sorted1, N2C, g_mean1); }

// ================= mma.sync bf16-split K-concat GEMM =================
// out[m][n] = [Aself|Aneigh][m] @ [Ws;Wn][n] + b (+relu layer0), K' = 256.
// fp32 -> bf16 hi+lo, 3 chains: Ah*Wh + Al*Wh + Ah*Wl, fp32 HMMA accumulate.
//
// smem (192 KB):
//   [0)      W'h [128 n][256 k] bf16 (64 KB);  [65536)  W'l (64 KB)
//   [131072) A'h [64 m][256 k]  bf16 (32 KB);  [163840) A'l (32 KB)
// rows are 512 B = 32 x 16B chunks; chunk index swizzle: c ^= (row&7).
#define GW_OFF 0
#define GA_OFF 131072
#define GSMEM  196608

__device__ __forceinline__ uint32_t smem_u32(const void* p) {
    uint32_t a;
    asm("{ .reg .u64 t; cvta.to.shared.u64 t, %1; cvt.u32.u64 %0, t; }" : "=r"(a) : "l"(p));
    return a;
}
__device__ __forceinline__ uint32_t swz512(int row, int k) {  // k = even bf16 col 0..254
    uint32_t chunk = ((uint32_t)(k >> 3)) ^ ((uint32_t)row & 7u);
    return (uint32_t)row * 512u + chunk * 16u + (uint32_t)(k & 7) * 2u;
}
__device__ __forceinline__ void split2(float a, float b, uint32_t& h, uint32_t& l) {
    __nv_bfloat16 ah = __float2bfloat16(a), bh = __float2bfloat16(b);
    float ar = a - __bfloat162float(ah);
    float br = b - __bfloat162float(bh);
    __nv_bfloat16 al = __float2bfloat16(ar), bl = __float2bfloat16(br);
    h = (uint32_t)__bfloat16_as_ushort(ah) | ((uint32_t)__bfloat16_as_ushort(bh) << 16);
    l = (uint32_t)__bfloat16_as_ushort(al) | ((uint32_t)__bfloat16_as_ushort(bl) << 16);
}
__device__ __forceinline__ void ldsm4(uint32_t* r, uint32_t addr) {
    asm volatile("ldmatrix.sync.aligned.m8n8.x4.shared.b16 {%0,%1,%2,%3}, [%4];"
                 : "=r"(r[0]), "=r"(r[1]), "=r"(r[2]), "=r"(r[3]) : "r"(addr));
}
__device__ __forceinline__ void mma16816(float* d, const uint32_t* a, uint32_t b0, uint32_t b1) {
    asm volatile("mma.sync.aligned.m16n8k16.row.col.f32.bf16.bf16.f32 "
                 "{%0,%1,%2,%3}, {%4,%5,%6,%7}, {%8,%9}, {%0,%1,%2,%3};"
                 : "+f"(d[0]), "+f"(d[1]), "+f"(d[2]), "+f"(d[3])
                 : "r"(a[0]), "r"(a[1]), "r"(a[2]), "r"(a[3]), "r"(b0), "r"(b1));
}

template <int LAYER>
__global__ void __launch_bounds__(256, 1) mgemm_k(const float* __restrict__ nf,
                                                  const int* __restrict__ inode,
                                                  const float* __restrict__ Ws,
                                                  const float* __restrict__ Wn,
                                                  const float* __restrict__ bias) {
    extern __shared__ char sm[];
    uint32_t smb = smem_u32(sm);
    int tid = threadIdx.x;
    int wid = tid >> 5;
    int lane = tid & 31;
    int m0 = blockIdx.x * 64;

    const float* __restrict__ Aself  = (LAYER == 0) ? nf : g_h1;
    const float* __restrict__ Aneigh = (LAYER == 0) ? g_mean0 : g_mean1;
    float* __restrict__ outp = (LAYER == 0) ? g_h1 : g_h2;

    // ---- W' tile: [Ws;Wn] fp32 [k'][n] -> bf16 hi/lo [n][k'=256], swizzled ----
    for (int p = tid; p < 16384; p += 256) {
        int n = p & 127;
        int k = (p >> 7) * 2;             // 0..254 even
        float x0, x1;
        if (k < 128) { x0 = Ws[k * 128 + n];         x1 = Ws[(k + 1) * 128 + n]; }
        else         { x0 = Wn[(k - 128) * 128 + n]; x1 = Wn[(k - 127) * 128 + n]; }
        uint32_t h, l;
        split2(x0, x1, h, l);
        uint32_t off = swz512(n, k);
        *(uint32_t*)(sm + GW_OFF + off) = h;
        *(uint32_t*)(sm + GW_OFF + 65536 + off) = l;
    }

    // ---- A' tile: 64 rows x 256 k' (self k'<128, neigh k'>=128), hi/lo ----
    {
        int r = tid >> 2;                 // local row 0..63
        int j = tid & 3;                  // quarter: k' = j*64 .. j*64+63
        int k0 = j * 64;
        const float* src;
        if (j < 2) {
            long selfRow = (LAYER == 0) ? (long)inode[m0 + r] : (long)(m0 + r);
            src = Aself + selfRow * 128 + j * 64;
        } else {
            src = Aneigh + (long)(m0 + r) * 128 + (j - 2) * 64;
        }
        const float4* s4 = (const float4*)src;
#pragma unroll
        for (int q = 0; q < 16; q++) {
            float4 v = s4[q];
            int k = k0 + q * 4;
            uint32_t h, l;
            uint32_t o0 = swz512(r, k);
            uint32_t o1 = swz512(r, k + 2);
            split2(v.x, v.y, h, l);
            *(uint32_t*)(sm + GA_OFF + o0) = h;  *(uint32_t*)(sm + GA_OFF + 32768 + o0) = l;
            split2(v.z, v.w, h, l);
            *(uint32_t*)(sm + GA_OFF + o1) = h;  *(uint32_t*)(sm + GA_OFF + 32768 + o1) = l;
        }
    }
    __syncthreads();

    // ---- warp tiling: 2(m) x 4(n): warp tile 32m x 32n ----
    int warp_m = wid & 1;
    int warp_n = wid >> 1;
    int lr = lane & 7;
    int quad = lane >> 3;

    float d[2][4][4];
#pragma unroll
    for (int mt = 0; mt < 2; mt++)
#pragma unroll
        for (int nt = 0; nt < 4; nt++)
#pragma unroll
            for (int j = 0; j < 4; j++) d[mt][nt][j] = 0.f;

    // A lane pattern: x4 = (m8 tiles 0/1 at chunk+0, then chunk+1)
    int aq = quad >> 1;                       // chunk +0/+1
    int arow0 = warp_m * 32 + (quad & 1) * 8 + lr;        // mt adds +16
    // B lane pattern: x4 = (n8 tile0 k0,k1, n8 tile1 k0,k1)
    int bq = quad & 1;
    int brow0 = warp_n * 32 + (quad >> 1) * 8 + lr;       // g adds +16

#pragma unroll
    for (int s = 0; s < 16; s++) {
        int kc = s * 2;
        uint32_t ah[2][4], al[2][4];
#pragma unroll
        for (int mt = 0; mt < 2; mt++) {
            int arow = arow0 + mt * 16;
            uint32_t aoff = smb + GA_OFF + (uint32_t)arow * 512u +
                            ((uint32_t)((kc + aq) ^ (arow & 7))) * 16u;
            ldsm4(ah[mt], aoff);
            ldsm4(al[mt], aoff + 32768u);
        }
        uint32_t bh[2][4], bl[2][4];
#pragma unroll
        for (int g = 0; g < 2; g++) {
            int brow = brow0 + g * 16;
            uint32_t boff = smb + GW_OFF + (uint32_t)brow * 512u +
                            ((uint32_t)((kc + bq) ^ (brow & 7))) * 16u;
            ldsm4(bh[g], boff);
            ldsm4(bl[g], boff + 65536u);
        }
#pragma unroll
        for (int mt = 0; mt < 2; mt++)
#pragma unroll
            for (int g = 0; g < 2; g++)
#pragma unroll
                for (int t = 0; t < 2; t++) {
                    float* dd = d[mt][g * 2 + t];
                    uint32_t b0h = bh[g][2 * t], b1h = bh[g][2 * t + 1];
                    uint32_t b0l = bl[g][2 * t], b1l = bl[g][2 * t + 1];
                    mma16816(dd, ah[mt], b0h, b1h);
                    mma16816(dd, al[mt], b0h, b1h);
                    mma16816(dd, ah[mt], b0l, b1l);
                }
    }

    // ---- epilogue: bias (+relu), store ----
    int group = lane >> 2;
#pragma unroll
    for (int mt = 0; mt < 2; mt++) {
        long rowA = (long)(m0 + warp_m * 32 + mt * 16 + group);
        long rowB = rowA + 8;
#pragma unroll
        for (int nt = 0; nt < 4; nt++) {
            int c = warp_n * 32 + nt * 8 + (lane & 3) * 2;
            float bx = bias[c], by = bias[c + 1];
            float2 oA, oB;
            oA.x = d[mt][nt][0] + bx; oA.y = d[mt][nt][1] + by;
            oB.x = d[mt][nt][2] + bx; oB.y = d[mt][nt][3] + by;
            if (LAYER == 0) {
                oA.x = fmaxf(oA.x, 0.f); oA.y = fmaxf(oA.y, 0.f);
                oB.x = fmaxf(oB.x, 0.f); oB.y = fmaxf(oB.y, 0.f);
            }
            *(float2*)&outp[rowA * 128 + c] = oA;
            *(float2*)&outp[rowB * 128 + c] = oB;
        }
    }
}

// ---------------- final pos/neg gathers ----------------
__global__ void out_k(const int* __restrict__ ps, const int* __restrict__ pd,
                      const int* __restrict__ ns, const int* __restrict__ nd,
                      float* __restrict__ out) {
    int w = (int)((blockIdx.x * (long)blockDim.x + threadIdx.x) >> 5);
    int lane = threadIdx.x & 31;
    int grp = w >> 12;
    int r = w & (PC - 1);
    const int* tab = (grp == 0) ? ps : (grp == 1) ? pd : (grp == 2) ? ns : nd;
    long src = tab[r];
    float4 v = ((const float4*)g_h2)[src * 32 + lane];
    ((float4*)out)[(long)w * 32 + lane] = v;
}

// ---------------- launch ----------------
extern "C" void kernel_launch(void* const* d_in, const int* in_sizes, int n_in,
                              void* d_out, int out_size) {
    const float* nf    = (const float*)d_in[0];
    const int*   inode = (const int*)d_in[1];
    const int*   esrc0 = (const int*)d_in[2];
    const int*   edst0 = (const int*)d_in[3];
    const int*   esrc1 = (const int*)d_in[4];
    const int*   edst1 = (const int*)d_in[5];
    const int*   ps    = (const int*)d_in[6];
    const int*   pd    = (const int*)d_in[7];
    const int*   ns    = (const int*)d_in[8];
    const int*   nd    = (const int*)d_in[9];
    const float* Ws0   = (const float*)d_in[10];
    const float* Wn0   = (const float*)d_in[11];
    const float* b0    = (const float*)d_in[12];
    const float* Ws1   = (const float*)d_in[13];
    const float* Wn1   = (const float*)d_in[14];
    const float* b1    = (const float*)d_in[15];
    float* out = (float*)d_out;

    cudaFuncSetAttribute(reinterpret_cast<const void*>(mgemm_k<0>),
                         cudaFuncAttributeMaxDynamicSharedMemorySize, GSMEM);
    cudaFuncSetAttribute(reinterpret_cast<const void*>(mgemm_k<1>),
                         cudaFuncAttributeMaxDynamicSharedMemorySize, GSMEM);

    void *p0 = nullptr, *p1 = nullptr;
    cudaGetSymbolAddress(&p0, g_hist0);
    cudaGetSymbolAddress(&p1, g_hist1);
    cudaMemsetAsync(p0, 0, N1C * sizeof(int));
    cudaMemsetAsync(p1, 0, N2C * sizeof(int));

    histF_k<<<(E0C + E1C) / 256, 256>>>(edst0, edst1);
    scanA_k<<<NBS, 256>>>();
    scanB_k<<<1, NBS>>>();
    scanC_k<<<NBS, 256>>>();
    scatF_k<<<(E0C + E1C) / 256, 256>>>(esrc0, edst0, esrc1, edst1, inode);
    agg0_k<<<(N1C * 32 + 255) / 256, 256>>>(nf);
    mgemm_k<0><<<N1C / 64, 256, GSMEM>>>(nf, inode, Ws0, Wn0, b0);
    agg1_k<<<(N2C * 32 + 255) / 256, 256>>>();
    mgemm_k<1><<<N2C / 64, 256, GSMEM>>>(nf, inode, Ws1, Wn1, b1);
    out_k<<<(4 * PC * 32) / 256, 256>>>(ps, pd, ns, nd, out);
}

// round 14
// speedup vs baseline: 1.4429x; 1.4429x over previous
#include <cuda_runtime.h>
#include <cuda_bf16.h>
#include <cstdint>

#define NTOT 1000000
#define N0C  495616
#define N1C  45056
#define N2C  4096
#define E0C  450560
#define E1C  40960
#define DC   128
#define PC   4096

#define NB0  (N1C / 256)        // 176
#define NB1  (N2C / 256)        // 16
#define NBS  (NB0 + NB1)        // 192

// ---------------- device scratch (static, allocation-free) ----------------
__device__ float g_mean0[N1C * DC];
__device__ float g_h1[N1C * DC];
__device__ float g_mean1[N2C * DC];
__device__ float g_h2[N2C * DC];
__device__ int   g_histC[N1C + N2C];      // fused hist: [0,N1C) graph0, [N1C,..) graph1
__device__ int   g_off0[N1C + 1];
__device__ int   g_cur0[N1C];
__device__ int   g_off1[N2C + 1];
__device__ int   g_cur1[N2C];
__device__ int   g_sorted0[E0C];
__device__ int   g_sorted1[E1C];
__device__ int   g_part[NBS];
__device__ uint32_t g_wt[2][32768];       // precomputed W bf16 hi/lo tiles, 131072 B per layer

// ---------------- fused histogram over both edge lists ----------------
__global__ void histF_k(const int* __restrict__ ed0, const int* __restrict__ ed1) {
    int e = blockIdx.x * 256 + threadIdx.x;
    if (e < E0C) atomicAdd(&g_histC[ed0[e]], 1);
    else         atomicAdd(&g_histC[N1C + ed1[e - E0C]], 1);
}

// ---------------- scanA: per-block sums ----------------
__global__ void scanA_k() {
    __shared__ int red[256];
    int b = blockIdx.x, t = threadIdx.x;
    int v = g_histC[b * 256 + t];
    red[t] = v; __syncthreads();
#pragma unroll
    for (int d = 128; d > 0; d >>= 1) {
        if (t < d) red[t] += red[t + d];
        __syncthreads();
    }
    if (t == 0) g_part[b] = red[0];
}

// ---------------- scanC2: each block scans partials itself + local scan ----------------
__global__ void scanC2_k() {
    __shared__ int sp[256];
    __shared__ int s[256];
    int b = blockIdx.x, t = threadIdx.x;

    // scan the 192 block partials (Hillis-Steele over shared)
    sp[t] = (t < NBS) ? g_part[t] : 0;
    __syncthreads();
#pragma unroll
    for (int d = 1; d < 256; d <<= 1) {
        int x = (t >= d) ? sp[t - d] : 0;
        __syncthreads();
        sp[t] += x;
        __syncthreads();
    }
    int tot0 = sp[NB0 - 1];
    int tot1 = sp[NBS - 1] - tot0;
    bool is0 = (b < NB0);
    int blkExcl = (b == 0) ? 0 : sp[b - 1];
    if (!is0) blkExcl -= tot0;

    // local scan of this block's 256 hist entries
    int i = b * 256 + t;                       // global fused index
    int v = g_histC[i];
    s[t] = v; __syncthreads();
#pragma unroll
    for (int d = 1; d < 256; d <<= 1) {
        int x = (t >= d) ? s[t - d] : 0;
        __syncthreads();
        s[t] += x;
        __syncthreads();
    }
    int off = s[t] - v + blkExcl;
    if (is0) { g_off0[i] = off; g_cur0[i] = off; }
    else     { int j = i - N1C; g_off1[j] = off; g_cur1[j] = off; }
    if (t == 255) {
        if (b == NB0 - 1) g_off0[N1C] = tot0;
        if (b == NBS - 1) g_off1[N2C] = tot1;
    }
}

// ---------------- fused scatter ----------------
__global__ void scatF_k(const int* __restrict__ es0, const int* __restrict__ ed0,
                        const int* __restrict__ es1, const int* __restrict__ ed1,
                        const int* __restrict__ inode) {
    int e = blockIdx.x * 256 + threadIdx.x;
    if (e < E0C) {
        int d = ed0[e];
        int p = atomicAdd(&g_cur0[d], 1);
        g_sorted0[p] = inode[es0[e]];
    } else {
        int k = e - E0C;
        int d = ed1[k];
        int p = atomicAdd(&g_cur1[d], 1);
        g_sorted1[p] = es1[k];
    }
}

// ---------------- neighbor mean aggregation: one warp per dst ----------------
__device__ __forceinline__ void agg_body(const float* __restrict__ feat,
                                         const int* __restrict__ offs,
                                         const int* __restrict__ sorted,
                                         int n_dst, float* __restrict__ mean_out) {
    int w = (int)((blockIdx.x * (long)blockDim.x + threadIdx.x) >> 5);
    int lane = threadIdx.x & 31;
    if (w >= n_dst) return;
    int beg = offs[w], end = offs[w + 1];
    const float4* f4 = (const float4*)feat;
    float4 acc = make_float4(0.f, 0.f, 0.f, 0.f);
    for (int j = beg; j < end; j++) {
        long r = sorted[j];
        float4 v = f4[r * 32 + lane];
        acc.x += v.x; acc.y += v.y; acc.z += v.z; acc.w += v.w;
    }
    float deg = (float)(end - beg);
    float sc = 1.0f / fmaxf(deg, 1.0f);
    ((float4*)mean_out)[(long)w * 32 + lane] =
        make_float4(acc.x * sc, acc.y * sc, acc.z * sc, acc.w * sc);
}
__global__ void agg0_k(const float* __restrict__ nf) { agg_body(nf, g_off0, g_sorted0, N1C, g_mean0); }
__global__ void agg1_k() { agg_body(g_h1, g_off1, g_sorted1, N2C, g_mean1); }

// ================= W tile precompute (once, both layers) =================
// Produces the exact bytes mgemm wants in smem: 4 tiles (Wsh, Wsl, Wnh, Wnl),
// each [128 n][128 k] bf16 swizzled 256B rows; tile base = mat*65536 (+32768 lo).
__device__ __forceinline__ uint32_t swz_addr(int row, int k) {   // k = even bf16 col
    uint32_t chunk = ((uint32_t)(k >> 3)) ^ ((uint32_t)row & 7u);
    return (uint32_t)row * 256u + chunk * 16u + (uint32_t)(k & 7) * 2u;
}
__device__ __forceinline__ void split2v(float a, float b, uint32_t& h, uint32_t& l) {
    __nv_bfloat16 ah = __float2bfloat16(a), bh = __float2bfloat16(b);
    float ar = a - __bfloat162float(ah);
    float br = b - __bfloat162float(bh);
    __nv_bfloat16 al = __float2bfloat16(ar), bl = __float2bfloat16(br);
    h = (uint32_t)__bfloat16_as_ushort(ah) | ((uint32_t)__bfloat16_as_ushort(bh) << 16);
    l = (uint32_t)__bfloat16_as_ushort(al) | ((uint32_t)__bfloat16_as_ushort(bl) << 16);
}

__global__ void wprep_k(const float* __restrict__ Ws0, const float* __restrict__ Wn0,
                        const float* __restrict__ Ws1, const float* __restrict__ Wn1) {
    int g = blockIdx.x * 256 + threadIdx.x;      // 0..32767
    int layer = g >> 14;
    int p = g & 16383;
    int mat = p >> 13;
    int q = p & 8191;
    int n = q & 127;
    int k = (q >> 7) * 2;
    const float* W = layer ? (mat ? Wn1 : Ws1) : (mat ? Wn0 : Ws0);
    float x0 = W[k * 128 + n];
    float x1 = W[(k + 1) * 128 + n];
    uint32_t h, l;
    split2v(x0, x1, h, l);
    uint32_t off = swz_addr(n, k);
    char* base = (char*)g_wt + layer * 131072 + mat * 65536;
    *(uint32_t*)(base + off) = h;
    *(uint32_t*)(base + 32768 + off) = l;
}

// ================= mma.sync bf16-split dual-A GEMM (R8 structure) =================
#define GW_OFF 0
#define GA_OFF 131072
#define GSMEM  196608

__device__ __forceinline__ uint32_t smem_u32(const void* p) {
    uint32_t a;
    asm("{ .reg .u64 t; cvta.to.shared.u64 t, %1; cvt.u32.u64 %0, t; }" : "=r"(a) : "l"(p));
    return a;
}
__device__ __forceinline__ void ldsm4(uint32_t* r, uint32_t addr) {
    asm volatile("ldmatrix.sync.aligned.m8n8.x4.shared.b16 {%0,%1,%2,%3}, [%4];"
                 : "=r"(r[0]), "=r"(r[1]), "=r"(r[2]), "=r"(r[3]) : "r"(addr));
}
__device__ __forceinline__ void mma16816(float* d, const uint32_t* a, uint32_t b0, uint32_t b1) {
    asm volatile("mma.sync.aligned.m16n8k16.row.col.f32.bf16.bf16.f32 "
                 "{%0,%1,%2,%3}, {%4,%5,%6,%7}, {%8,%9}, {%0,%1,%2,%3};"
                 : "+f"(d[0]), "+f"(d[1]), "+f"(d[2]), "+f"(d[3])
                 : "r"(a[0]), "r"(a[1]), "r"(a[2]), "r"(a[3]), "r"(b0), "r"(b1));
}

template <int LAYER>
__global__ void __launch_bounds__(256, 1) mgemm_k(const float* __restrict__ nf,
                                                  const int* __restrict__ inode,
                                                  const float* __restrict__ bias) {
    extern __shared__ char sm[];
    uint32_t smb = smem_u32(sm);
    int tid = threadIdx.x;
    int wid = tid >> 5;
    int lane = tid & 31;
    int m0 = blockIdx.x * 64;

    const float* __restrict__ Aself  = (LAYER == 0) ? nf : g_h1;
    const float* __restrict__ Aneigh = (LAYER == 0) ? g_mean0 : g_mean1;
    float* __restrict__ outp = (LAYER == 0) ? g_h1 : g_h2;

    // ---- W tiles: straight float4 copy of precomputed swizzled bytes ----
    {
        const uint4* src = (const uint4*)((const char*)g_wt + LAYER * 131072);
        uint4* dst = (uint4*)(sm + GW_OFF);
#pragma unroll 8
        for (int i = tid; i < 8192; i += 256) dst[i] = src[i];
    }

    // ---- A tiles: 64 rows x 128 k, self + neigh, hi/lo ----
    {
        int r = tid >> 2;                 // local row 0..63
        int k0 = (tid & 3) * 32;          // 32 k per thread
        long selfRow = (LAYER == 0) ? (long)inode[m0 + r] : (long)(m0 + r);
        const float4* s4 = (const float4*)(Aself + selfRow * 128 + k0);
        const float4* n4 = (const float4*)(Aneigh + (long)(m0 + r) * 128 + k0);
        char* aS = sm + GA_OFF;           // Ash; +16384 Asl; +32768 Anh; +49152 Anl
#pragma unroll
        for (int q = 0; q < 8; q++) {
            float4 vs = s4[q];
            float4 vn = n4[q];
            int k = k0 + q * 4;
            uint32_t h, l;
            uint32_t o0 = swz_addr(r, k);
            uint32_t o1 = swz_addr(r, k + 2);
            split2v(vs.x, vs.y, h, l);
            *(uint32_t*)(aS + o0) = h;           *(uint32_t*)(aS + 16384 + o0) = l;
            split2v(vs.z, vs.w, h, l);
            *(uint32_t*)(aS + o1) = h;           *(uint32_t*)(aS + 16384 + o1) = l;
            split2v(vn.x, vn.y, h, l);
            *(uint32_t*)(aS + 32768 + o0) = h;   *(uint32_t*)(aS + 49152 + o0) = l;
            split2v(vn.z, vn.w, h, l);
            *(uint32_t*)(aS + 32768 + o1) = h;   *(uint32_t*)(aS + 49152 + o1) = l;
        }
    }
    __syncthreads();

    // ---- warp tiling: warp_m = wid&3 (16 rows), warp_n = wid>>2 (64 cols) ----
    int warp_m = wid & 3;
    int warp_n = wid >> 2;
    int lr = lane & 7;
    int quad = lane >> 3;

    float d[8][4];
#pragma unroll
    for (int f = 0; f < 8; f++)
#pragma unroll
        for (int j = 0; j < 4; j++) d[f][j] = 0.f;

    int arow = warp_m * 16 + (quad & 1) * 8 + lr;
    uint32_t abase = smb + GA_OFF + (uint32_t)arow * 256u;
    int arx = arow & 7;
    int aq = quad >> 1;

    int brow_base = warp_n * 64 + (quad >> 1) * 8 + lr;
    int bq = quad & 1;

#pragma unroll
    for (int s = 0; s < 8; s++) {
        int kc = s * 2;
        uint32_t ash[4], asl[4], anh[4], anl[4];
        uint32_t aoff = abase + ((uint32_t)((kc + aq) ^ arx)) * 16u;
        ldsm4(ash, aoff);
        ldsm4(asl, aoff + 16384u);
        ldsm4(anh, aoff + 32768u);
        ldsm4(anl, aoff + 49152u);
#pragma unroll
        for (int np = 0; np < 4; np++) {
            int brow = brow_base + np * 16;
            uint32_t boff = smb + GW_OFF + (uint32_t)brow * 256u +
                            ((uint32_t)((kc + bq) ^ (brow & 7))) * 16u;
            uint32_t bsh[4], bsl[4], bnh[4], bnl[4];
            ldsm4(bsh, boff);
            ldsm4(bsl, boff + 32768u);
            ldsm4(bnh, boff + 65536u);
            ldsm4(bnl, boff + 98304u);
#pragma unroll
            for (int t = 0; t < 2; t++) {
                float* dd = d[np * 2 + t];
                uint32_t b0h = bsh[2 * t], b1h = bsh[2 * t + 1];
                uint32_t b0l = bsl[2 * t], b1l = bsl[2 * t + 1];
                uint32_t n0h = bnh[2 * t], n1h = bnh[2 * t + 1];
                uint32_t n0l = bnl[2 * t], n1l = bnl[2 * t + 1];
                mma16816(dd, ash, b0h, b1h);
                mma16816(dd, asl, b0h, b1h);
                mma16816(dd, ash, b0l, b1l);
                mma16816(dd, anh, n0h, n1h);
                mma16816(dd, anl, n0h, n1h);
                mma16816(dd, anh, n0l, n1l);
            }
        }
    }

    // ---- epilogue: bias (+relu), store ----
    int group = lane >> 2;
    int col0 = warp_n * 64 + (lane & 3) * 2;
    long rowA = (long)(m0 + warp_m * 16 + group);
    long rowB = rowA + 8;
#pragma unroll
    for (int f = 0; f < 8; f++) {
        int c = col0 + f * 8;
        float bx = bias[c], by = bias[c + 1];
        float2 oA, oB;
        oA.x = d[f][0] + bx; oA.y = d[f][1] + by;
        oB.x = d[f][2] + bx; oB.y = d[f][3] + by;
        if (LAYER == 0) {
            oA.x = fmaxf(oA.x, 0.f); oA.y = fmaxf(oA.y, 0.f);
            oB.x = fmaxf(oB.x, 0.f); oB.y = fmaxf(oB.y, 0.f);
        }
        *(float2*)&outp[rowA * 128 + c] = oA;
        *(float2*)&outp[rowB * 128 + c] = oB;
    }
}

// ---------------- final pos/neg gathers ----------------
__global__ void out_k(const int* __restrict__ ps, const int* __restrict__ pd,
                      const int* __restrict__ ns, const int* __restrict__ nd,
                      float* __restrict__ out) {
    int w = (int)((blockIdx.x * (long)blockDim.x + threadIdx.x) >> 5);
    int lane = threadIdx.x & 31;
    int grp = w >> 12;
    int r = w & (PC - 1);
    const int* tab = (grp == 0) ? ps : (grp == 1) ? pd : (grp == 2) ? ns : nd;
    long src = tab[r];
    float4 v = ((const float4*)g_h2)[src * 32 + lane];
    ((float4*)out)[(long)w * 32 + lane] = v;
}

// ---------------- launch ----------------
extern "C" void kernel_launch(void* const* d_in, const int* in_sizes, int n_in,
                              void* d_out, int out_size) {
    const float* nf    = (const float*)d_in[0];
    const int*   inode = (const int*)d_in[1];
    const int*   esrc0 = (const int*)d_in[2];
    const int*   edst0 = (const int*)d_in[3];
    const int*   esrc1 = (const int*)d_in[4];
    const int*   edst1 = (const int*)d_in[5];
    const int*   ps    = (const int*)d_in[6];
    const int*   pd    = (const int*)d_in[7];
    const int*   ns    = (const int*)d_in[8];
    const int*   nd    = (const int*)d_in[9];
    const float* Ws0   = (const float*)d_in[10];
    const float* Wn0   = (const float*)d_in[11];
    const float* b0    = (const float*)d_in[12];
    const float* Ws1   = (const float*)d_in[13];
    const float* Wn1   = (const float*)d_in[14];
    const float* b1    = (const float*)d_in[15];
    float* out = (float*)d_out;

    cudaFuncSetAttribute(reinterpret_cast<const void*>(mgemm_k<0>),
                         cudaFuncAttributeMaxDynamicSharedMemorySize, GSMEM);
    cudaFuncSetAttribute(reinterpret_cast<const void*>(mgemm_k<1>),
                         cudaFuncAttributeMaxDynamicSharedMemorySize, GSMEM);

    void* ph = nullptr;
    cudaGetSymbolAddress(&ph, g_histC);
    cudaMemsetAsync(ph, 0, (N1C + N2C) * sizeof(int));                    // launch 1

    histF_k<<<(E0C + E1C) / 256, 256>>>(edst0, edst1);                    // 2
    scanA_k<<<NBS, 256>>>();                                              // 3
    scanC2_k<<<NBS, 256>>>();                                             // 4
    scatF_k<<<(E0C + E1C) / 256, 256>>>(esrc0, edst0, esrc1, edst1, inode); // 5
    agg0_k<<<(N1C * 32 + 255) / 256, 256>>>(nf);                          // 6  <- ncu profiles this
    wprep_k<<<128, 256>>>(Ws0, Wn0, Ws1, Wn1);                            // 7
    mgemm_k<0><<<N1C / 64, 256, GSMEM>>>(nf, inode, b0);                  // 8
    agg1_k<<<(N2C * 32 + 255) / 256, 256>>>();                            // 9
    mgemm_k<1><<<N2C / 64, 256, GSMEM>>>(nf, inode, b1);                  // 10
    out_k<<<(4 * PC * 32) / 256, 256>>>(ps, pd, ns, nd, out);             // 11
}

// round 15
// speedup vs baseline: 1.4918x; 1.0339x over previous
#include <cuda_runtime.h>
#include <cuda_bf16.h>
#include <cstdint>

#define NTOT 1000000
#define N0C  495616
#define N1C  45056
#define N2C  4096
#define E0C  450560
#define E1C  40960
#define DC   128
#define PC   4096

#define NB0  (N1C / 256)        // 176
#define NB1  (N2C / 256)        // 16
#define NBS  (NB0 + NB1)        // 192

// ---------------- device scratch (static, allocation-free) ----------------
__device__ float g_mean0[N1C * DC];
__device__ float g_h1[N1C * DC];
__device__ float g_mean1[N2C * DC];
__device__ float g_h2[N2C * DC];
__device__ int   g_histC[N1C + N2C];      // fused hist: [0,N1C) graph0, [N1C,..) graph1
__device__ int   g_off0[N1C + 1];
__device__ int   g_cur0[N1C];
__device__ int   g_off1[N2C + 1];
__device__ int   g_cur1[N2C];
__device__ int   g_sorted0[E0C];
__device__ int   g_sorted1[E1C];
__device__ int   g_part[NBS];
__device__ uint32_t g_wt[2][32768];       // precomputed W bf16 hi/lo tiles, 131072 B per layer

// ---------------- helpers ----------------
__device__ __forceinline__ uint32_t swz_addr(int row, int k) {   // k = even bf16 col
    uint32_t chunk = ((uint32_t)(k >> 3)) ^ ((uint32_t)row & 7u);
    return (uint32_t)row * 256u + chunk * 16u + (uint32_t)(k & 7) * 2u;
}
__device__ __forceinline__ void split2v(float a, float b, uint32_t& h, uint32_t& l) {
    __nv_bfloat16 ah = __float2bfloat16(a), bh = __float2bfloat16(b);
    float ar = a - __bfloat162float(ah);
    float br = b - __bfloat162float(bh);
    __nv_bfloat16 al = __float2bfloat16(ar), bl = __float2bfloat16(br);
    h = (uint32_t)__bfloat16_as_ushort(ah) | ((uint32_t)__bfloat16_as_ushort(bh) << 16);
    l = (uint32_t)__bfloat16_as_ushort(al) | ((uint32_t)__bfloat16_as_ushort(bl) << 16);
}

// ---------------- prep: zero hist + W tile precompute (launch 1) ----------------
__global__ void prep_k(const float* __restrict__ Ws0, const float* __restrict__ Wn0,
                       const float* __restrict__ Ws1, const float* __restrict__ Wn1) {
    int g = blockIdx.x * 256 + threadIdx.x;      // 0..49151
    g_histC[g] = 0;                              // N1C+N2C == 49152 exactly
    if (g < 32768) {
        int layer = g >> 14;
        int p = g & 16383;
        int mat = p >> 13;
        int q = p & 8191;
        int n = q & 127;
        int k = (q >> 7) * 2;
        const float* W = layer ? (mat ? Wn1 : Ws1) : (mat ? Wn0 : Ws0);
        float x0 = W[k * 128 + n];
        float x1 = W[(k + 1) * 128 + n];
        uint32_t h, l;
        split2v(x0, x1, h, l);
        uint32_t off = swz_addr(n, k);
        char* base = (char*)g_wt + layer * 131072 + mat * 65536;
        *(uint32_t*)(base + off) = h;
        *(uint32_t*)(base + 32768 + off) = l;
    }
}

// ---------------- fused histogram, 4 edges/thread ----------------
__device__ __forceinline__ void hist1(int e, const int* __restrict__ ed0,
                                      const int* __restrict__ ed1) {
    if (e < E0C) atomicAdd(&g_histC[ed0[e]], 1);
    else         atomicAdd(&g_histC[N1C + ed1[e - E0C]], 1);
}
__global__ void histF_k(const int* __restrict__ ed0, const int* __restrict__ ed1) {
    int base = blockIdx.x * 1024 + threadIdx.x;
    hist1(base, ed0, ed1);
    hist1(base + 256, ed0, ed1);
    hist1(base + 512, ed0, ed1);
    hist1(base + 768, ed0, ed1);
}

// ---------------- scanA: per-block sums ----------------
__global__ void scanA_k() {
    __shared__ int red[256];
    int b = blockIdx.x, t = threadIdx.x;
    int v = g_histC[b * 256 + t];
    red[t] = v; __syncthreads();
#pragma unroll
    for (int d = 128; d > 0; d >>= 1) {
        if (t < d) red[t] += red[t + d];
        __syncthreads();
    }
    if (t == 0) g_part[b] = red[0];
}

// ---------------- scanC2: each block scans partials itself + local scan ----------------
__global__ void scanC2_k() {
    __shared__ int sp[256];
    __shared__ int s[256];
    int b = blockIdx.x, t = threadIdx.x;

    sp[t] = (t < NBS) ? g_part[t] : 0;
    __syncthreads();
#pragma unroll
    for (int d = 1; d < 256; d <<= 1) {
        int x = (t >= d) ? sp[t - d] : 0;
        __syncthreads();
        sp[t] += x;
        __syncthreads();
    }
    int tot0 = sp[NB0 - 1];
    int tot1 = sp[NBS - 1] - tot0;
    bool is0 = (b < NB0);
    int blkExcl = (b == 0) ? 0 : sp[b - 1];
    if (!is0) blkExcl -= tot0;

    int i = b * 256 + t;
    int v = g_histC[i];
    s[t] = v; __syncthreads();
#pragma unroll
    for (int d = 1; d < 256; d <<= 1) {
        int x = (t >= d) ? s[t - d] : 0;
        __syncthreads();
        s[t] += x;
        __syncthreads();
    }
    int off = s[t] - v + blkExcl;
    if (is0) { g_off0[i] = off; g_cur0[i] = off; }
    else     { int j = i - N1C; g_off1[j] = off; g_cur1[j] = off; }
    if (t == 255) {
        if (b == NB0 - 1) g_off0[N1C] = tot0;
        if (b == NBS - 1) g_off1[N2C] = tot1;
    }
}

// ---------------- fused scatter, 4 edges/thread ----------------
__device__ __forceinline__ void scat1(int e, const int* __restrict__ es0,
                                      const int* __restrict__ ed0,
                                      const int* __restrict__ es1,
                                      const int* __restrict__ ed1,
                                      const int* __restrict__ inode) {
    if (e < E0C) {
        int d = ed0[e];
        int p = atomicAdd(&g_cur0[d], 1);
        g_sorted0[p] = inode[es0[e]];
    } else {
        int k = e - E0C;
        int d = ed1[k];
        int p = atomicAdd(&g_cur1[d], 1);
        g_sorted1[p] = es1[k];
    }
}
__global__ void scatF_k(const int* __restrict__ es0, const int* __restrict__ ed0,
                        const int* __restrict__ es1, const int* __restrict__ ed1,
                        const int* __restrict__ inode) {
    int base = blockIdx.x * 1024 + threadIdx.x;
    scat1(base, es0, ed0, es1, ed1, inode);
    scat1(base + 256, es0, ed0, es1, ed1, inode);
    scat1(base + 512, es0, ed0, es1, ed1, inode);
    scat1(base + 768, es0, ed0, es1, ed1, inode);
}

// ---------------- neighbor mean aggregation: one warp per dst, MLP-4 ----------------
__device__ __forceinline__ void agg_body(const float* __restrict__ feat,
                                         const int* __restrict__ offs,
                                         const int* __restrict__ sorted,
                                         int n_dst, float* __restrict__ mean_out) {
    int w = (int)((blockIdx.x * (long)blockDim.x + threadIdx.x) >> 5);
    int lane = threadIdx.x & 31;
    if (w >= n_dst) return;
    int beg = offs[w], end = offs[w + 1];
    const float4* f4 = (const float4*)feat;
    float4 acc = make_float4(0.f, 0.f, 0.f, 0.f);
    int j = beg;
    for (; j + 4 <= end; j += 4) {
        long r0 = __ldg(sorted + j);
        long r1 = __ldg(sorted + j + 1);
        long r2 = __ldg(sorted + j + 2);
        long r3 = __ldg(sorted + j + 3);
        float4 v0 = f4[r0 * 32 + lane];
        float4 v1 = f4[r1 * 32 + lane];
        float4 v2 = f4[r2 * 32 + lane];
        float4 v3 = f4[r3 * 32 + lane];
        acc.x += v0.x + v1.x + v2.x + v3.x;
        acc.y += v0.y + v1.y + v2.y + v3.y;
        acc.z += v0.z + v1.z + v2.z + v3.z;
        acc.w += v0.w + v1.w + v2.w + v3.w;
    }
    for (; j < end; j++) {
        long r = __ldg(sorted + j);
        float4 v = f4[r * 32 + lane];
        acc.x += v.x; acc.y += v.y; acc.z += v.z; acc.w += v.w;
    }
    float deg = (float)(end - beg);
    float sc = 1.0f / fmaxf(deg, 1.0f);
    ((float4*)mean_out)[(long)w * 32 + lane] =
        make_float4(acc.x * sc, acc.y * sc, acc.z * sc, acc.w * sc);
}
__global__ void agg0_k(const float* __restrict__ nf) { agg_body(nf, g_off0, g_sorted0, N1C, g_mean0); }
__global__ void agg1_k() { agg_body(g_h1, g_off1, g_sorted1, N2C, g_mean1); }

// ================= mma.sync bf16-split dual-A GEMM =================
#define GW_OFF 0
#define GA_OFF 131072
#define GSMEM  196608

__device__ __forceinline__ uint32_t smem_u32(const void* p) {
    uint32_t a;
    asm("{ .reg .u64 t; cvta.to.shared.u64 t, %1; cvt.u32.u64 %0, t; }" : "=r"(a) : "l"(p));
    return a;
}
__device__ __forceinline__ void ldsm4(uint32_t* r, uint32_t addr) {
    asm volatile("ldmatrix.sync.aligned.m8n8.x4.shared.b16 {%0,%1,%2,%3}, [%4];"
                 : "=r"(r[0]), "=r"(r[1]), "=r"(r[2]), "=r"(r[3]) : "r"(addr));
}
__device__ __forceinline__ void mma16816(float* d, const uint32_t* a, uint32_t b0, uint32_t b1) {
    asm volatile("mma.sync.aligned.m16n8k16.row.col.f32.bf16.bf16.f32 "
                 "{%0,%1,%2,%3}, {%4,%5,%6,%7}, {%8,%9}, {%0,%1,%2,%3};"
                 : "+f"(d[0]), "+f"(d[1]), "+f"(d[2]), "+f"(d[3])
                 : "r"(a[0]), "r"(a[1]), "r"(a[2]), "r"(a[3]), "r"(b0), "r"(b1));
}

template <int LAYER>
__global__ void __launch_bounds__(256, 1) mgemm_k(const float* __restrict__ nf,
                                                  const int* __restrict__ inode,
                                                  const float* __restrict__ bias) {
    extern __shared__ char sm[];
    uint32_t smb = smem_u32(sm);
    int tid = threadIdx.x;
    int wid = tid >> 5;
    int lane = tid & 31;
    int m0 = blockIdx.x * 64;

    const float* __restrict__ Aself  = (LAYER == 0) ? nf : g_h1;
    const float* __restrict__ Aneigh = (LAYER == 0) ? g_mean0 : g_mean1;
    float* __restrict__ outp = (LAYER == 0) ? g_h1 : g_h2;

    // ---- W tiles: straight float4 copy of precomputed swizzled bytes ----
    {
        const uint4* src = (const uint4*)((const char*)g_wt + LAYER * 131072);
        uint4* dst = (uint4*)(sm + GW_OFF);
#pragma unroll 8
        for (int i = tid; i < 8192; i += 256) dst[i] = src[i];
    }

    // ---- A tiles: 64 rows x 128 k, self + neigh, hi/lo ----
    {
        int r = tid >> 2;                 // local row 0..63
        int k0 = (tid & 3) * 32;          // 32 k per thread
        long selfRow = (LAYER == 0) ? (long)inode[m0 + r] : (long)(m0 + r);
        const float4* s4 = (const float4*)(Aself + selfRow * 128 + k0);
        const float4* n4 = (const float4*)(Aneigh + (long)(m0 + r) * 128 + k0);
        char* aS = sm + GA_OFF;           // Ash; +16384 Asl; +32768 Anh; +49152 Anl
#pragma unroll
        for (int q = 0; q < 8; q++) {
            float4 vs = s4[q];
            float4 vn = n4[q];
            int k = k0 + q * 4;
            uint32_t h, l;
            uint32_t o0 = swz_addr(r, k);
            uint32_t o1 = swz_addr(r, k + 2);
            split2v(vs.x, vs.y, h, l);
            *(uint32_t*)(aS + o0) = h;           *(uint32_t*)(aS + 16384 + o0) = l;
            split2v(vs.z, vs.w, h, l);
            *(uint32_t*)(aS + o1) = h;           *(uint32_t*)(aS + 16384 + o1) = l;
            split2v(vn.x, vn.y, h, l);
            *(uint32_t*)(aS + 32768 + o0) = h;   *(uint32_t*)(aS + 49152 + o0) = l;
            split2v(vn.z, vn.w, h, l);
            *(uint32_t*)(aS + 32768 + o1) = h;   *(uint32_t*)(aS + 49152 + o1) = l;
        }
    }
    __syncthreads();

    // ---- warp tiling: warp_m = wid&3 (16 rows), warp_n = wid>>2 (64 cols) ----
    int warp_m = wid & 3;
    int warp_n = wid >> 2;
    int lr = lane & 7;
    int quad = lane >> 3;

    float d[8][4];
#pragma unroll
    for (int f = 0; f < 8; f++)
#pragma unroll
        for (int j = 0; j < 4; j++) d[f][j] = 0.f;

    int arow = warp_m * 16 + (quad & 1) * 8 + lr;
    uint32_t abase = smb + GA_OFF + (uint32_t)arow * 256u;
    int arx = arow & 7;
    int aq = quad >> 1;

    int brow_base = warp_n * 64 + (quad >> 1) * 8 + lr;
    int bq = quad & 1;

#pragma unroll
    for (int s = 0; s < 8; s++) {
        int kc = s * 2;
        uint32_t ash[4], asl[4], anh[4], anl[4];
        uint32_t aoff = abase + ((uint32_t)((kc + aq) ^ arx)) * 16u;
        ldsm4(ash, aoff);
        ldsm4(asl, aoff + 16384u);
        ldsm4(anh, aoff + 32768u);
        ldsm4(anl, aoff + 49152u);
#pragma unroll
        for (int np = 0; np < 4; np++) {
            int brow = brow_base + np * 16;
            uint32_t boff = smb + GW_OFF + (uint32_t)brow * 256u +
                            ((uint32_t)((kc + bq) ^ (brow & 7))) * 16u;
            uint32_t bsh[4], bsl[4], bnh[4], bnl[4];
            ldsm4(bsh, boff);
            ldsm4(bsl, boff + 32768u);
            ldsm4(bnh, boff + 65536u);
            ldsm4(bnl, boff + 98304u);
#pragma unroll
            for (int t = 0; t < 2; t++) {
                float* dd = d[np * 2 + t];
                uint32_t b0h = bsh[2 * t], b1h = bsh[2 * t + 1];
                uint32_t b0l = bsl[2 * t], b1l = bsl[2 * t + 1];
                uint32_t n0h = bnh[2 * t], n1h = bnh[2 * t + 1];
                uint32_t n0l = bnl[2 * t], n1l = bnl[2 * t + 1];
                mma16816(dd, ash, b0h, b1h);
                mma16816(dd, asl, b0h, b1h);
                mma16816(dd, ash, b0l, b1l);
                mma16816(dd, anh, n0h, n1h);
                mma16816(dd, anl, n0h, n1h);
                mma16816(dd, anh, n0l, n1l);
            }
        }
    }

    // ---- epilogue: bias (+relu), store ----
    int group = lane >> 2;
    int col0 = warp_n * 64 + (lane & 3) * 2;
    long rowA = (long)(m0 + warp_m * 16 + group);
    long rowB = rowA + 8;
#pragma unroll
    for (int f = 0; f < 8; f++) {
        int c = col0 + f * 8;
        float bx = bias[c], by = bias[c + 1];
        float2 oA, oB;
        oA.x = d[f][0] + bx; oA.y = d[f][1] + by;
        oB.x = d[f][2] + bx; oB.y = d[f][3] + by;
        if (LAYER == 0) {
            oA.x = fmaxf(oA.x, 0.f); oA.y = fmaxf(oA.y, 0.f);
            oB.x = fmaxf(oB.x, 0.f); oB.y = fmaxf(oB.y, 0.f);
        }
        *(float2*)&outp[rowA * 128 + c] = oA;
        *(float2*)&outp[rowB * 128 + c] = oB;
    }
}

// ---------------- final pos/neg gathers ----------------
__global__ void out_k(const int* __restrict__ ps, const int* __restrict__ pd,
                      const int* __restrict__ ns, const int* __restrict__ nd,
                      float* __restrict__ out) {
    int w = (int)((blockIdx.x * (long)blockDim.x + threadIdx.x) >> 5);
    int lane = threadIdx.x & 31;
    int grp = w >> 12;
    int r = w & (PC - 1);
    const int* tab = (grp == 0) ? ps : (grp == 1) ? pd : (grp == 2) ? ns : nd;
    long src = tab[r];
    float4 v = ((const float4*)g_h2)[src * 32 + lane];
    ((float4*)out)[(long)w * 32 + lane] = v;
}

// ---------------- launch ----------------
extern "C" void kernel_launch(void* const* d_in, const int* in_sizes, int n_in,
                              void* d_out, int out_size) {
    const float* nf    = (const float*)d_in[0];
    const int*   inode = (const int*)d_in[1];
    const int*   esrc0 = (const int*)d_in[2];
    const int*   edst0 = (const int*)d_in[3];
    const int*   esrc1 = (const int*)d_in[4];
    const int*   edst1 = (const int*)d_in[5];
    const int*   ps    = (const int*)d_in[6];
    const int*   pd    = (const int*)d_in[7];
    const int*   ns    = (const int*)d_in[8];
    const int*   nd    = (const int*)d_in[9];
    const float* Ws0   = (const float*)d_in[10];
    const float* Wn0   = (const float*)d_in[11];
    const float* b0    = (const float*)d_in[12];
    const float* Ws1   = (const float*)d_in[13];
    const float* Wn1   = (const float*)d_in[14];
    const float* b1    = (const float*)d_in[15];
    float* out = (float*)d_out;

    cudaFuncSetAttribute(reinterpret_cast<const void*>(mgemm_k<0>),
                         cudaFuncAttributeMaxDynamicSharedMemorySize, GSMEM);
    cudaFuncSetAttribute(reinterpret_cast<const void*>(mgemm_k<1>),
                         cudaFuncAttributeMaxDynamicSharedMemorySize, GSMEM);

    prep_k<<<192, 256>>>(Ws0, Wn0, Ws1, Wn1);                             // 1 (zero hist + wprep)
    histF_k<<<480, 256>>>(edst0, edst1);                                  // 2
    scanA_k<<<NBS, 256>>>();                                              // 3
    scanC2_k<<<NBS, 256>>>();                                             // 4
    scatF_k<<<480, 256>>>(esrc0, edst0, esrc1, edst1, inode);             // 5
    agg0_k<<<(N1C * 32 + 255) / 256, 256>>>(nf);                          // 6  <- ncu target
    mgemm_k<0><<<N1C / 64, 256, GSMEM>>>(nf, inode, b0);                  // 7
    agg1_k<<<(N2C * 32 + 255) / 256, 256>>>();                            // 8
    mgemm_k<1><<<N2C / 64, 256, GSMEM>>>(nf, inode, b1);                  // 9
    out_k<<<(4 * PC * 32) / 256, 256>>>(ps, pd, ns, nd, out);             // 10
}